// round 17
// baseline (speedup 1.0000x reference)
#include <cuda_runtime.h>
#include <cuda_fp16.h>
#include <cstdint>
#include <math.h>

#define SUB_NO 20
#define T_NO 201
#define E_NO 2000
#define I_NO 500
#define T_DATA 20000

// Output layout: concat of (V[20000], out_filters[40*201], C_syn_e[20*2000], C_syn_i[20*500])
#define OFF_F  (T_DATA)                   // 20000
#define OFF_CE (OFF_F + 40 * T_NO)        // 28040
#define OFF_CI (OFF_CE + SUB_NO * E_NO)   // 68040

#define PAD 48      // IIR warm-up: r^48 <= 2e-5 rel; tol is 1e-3

// ---------------- scratch ----------------
#define THE_N 40032   // >= 2001*20 halves, 16B-multiple (row 2000 = zero dummy)
#define THI_N 10032   // >= 501*20
__device__ __align__(16) __half g_THe[THE_N];
__device__ __align__(16) __half g_THi[THI_N];
__device__ float g_synZe[(PAD + T_DATA) * SUB_NO];
__device__ float g_synZi[(PAD + T_DATA) * SUB_NO];
__device__ int   g_A = 0;   // prep done
__device__ int   g_S = 0;   // spike phase done
__device__ int   g_C = 0;   // exit counter (last block resets all)

// param pack
#define P_GAIN  0
#define P_THETA 32
#define P_RE    64
#define P_BE    96
#define P_BDE   128
#define P_C1E   160
#define P_RI    192
#define P_BI    224
#define P_BDI   256
#define P_C1I   288
#define P_VO    320
__device__ float g_par[336];

#define N_PREP (E_NO + I_NO + 40 * T_NO + SUB_NO + 1)   // 10561

// ---------------- prep slice ----------------
__device__ void do_prep(int tid,
                        const float* __restrict__ Craw_e, const float* __restrict__ Craw_i,
                        const float* __restrict__ Wsyn, const float* __restrict__ Tausyn,
                        const float* __restrict__ Dsyn, const float* __restrict__ Wsub,
                        const float* __restrict__ Vo, const float* __restrict__ Theta,
                        float* __restrict__ out)
{
    if (tid < PAD * SUB_NO) {
        g_synZe[tid] = 0.f;
        g_synZi[tid] = 0.f;
    }

    if (tid < E_NO + I_NO) {
        const float* raw;
        float* o;
        __half* th;
        int stride, e;
        if (tid < E_NO) { raw = Craw_e; o = out + OFF_CE; th = g_THe; stride = E_NO; e = tid; }
        else            { raw = Craw_i; o = out + OFF_CI; th = g_THi; stride = I_NO; e = tid - E_NO; }
        float v[SUB_NO];
        float m = -1e30f;
#pragma unroll
        for (int j = 0; j < SUB_NO; ++j) { v[j] = raw[j * stride + e]; m = fmaxf(m, v[j]); }
        float s = 0.f;
#pragma unroll
        for (int j = 0; j < SUB_NO; ++j) { v[j] = expf(v[j] - m); s += v[j]; }
        float inv = 1.f / s;
#pragma unroll
        for (int j = 0; j < SUB_NO; ++j) {
            float w = v[j] * inv;
            o[j * stride + e]  = w;
            th[e * SUB_NO + j] = __float2half(w);
        }
    }

    int f = tid - (E_NO + I_NO);
    if (f >= 0 && f < 40 * T_NO) {
        int row  = f / T_NO;
        int k    = f - row * T_NO;
        int type = row / SUB_NO;
        int s    = row - type * SUB_NO;
        float delta = expf(Dsyn[s * 2 + type]);
        float tau   = expf(Tausyn[s * 2 + type]);
        float w     = expf(Wsyn[s * 2 + type]);
        float tt    = fmaxf((float)k - delta, 0.f) / tau;
        float val   = tt * expf(-tt) * w;
        if (type) val = -val;
        out[OFF_F + row * T_NO + k] = val;
    }

    int p = tid - (E_NO + I_NO + 40 * T_NO);
    if (p >= 0 && p < SUB_NO) {
        g_par[P_GAIN  + p] = expf(Wsub[p]);
        g_par[P_THETA + p] = Theta[p];
#pragma unroll
        for (int type = 0; type < 2; ++type) {
            float delta = expf(Dsyn[p * 2 + type]);
            float tau   = expf(Tausyn[p * 2 + type]);
            float w     = expf(Wsyn[p * 2 + type]);
            float r     = expf(-1.f / tau);
            float B     = w * expf(delta / tau) / tau;
            if (type) B = -B;
            float c1 = (delta > 1.f) ? B * (delta - 1.f) * r : 0.f;
            g_par[(type ? P_RI  : P_RE ) + p] = r;
            g_par[(type ? P_BI  : P_BE ) + p] = B;
            g_par[(type ? P_BDI : P_BDE) + p] = B * delta;
            g_par[(type ? P_C1I : P_C1E) + p] = c1;
        }
    }
    if (tid == N_PREP - 1) g_par[P_VO] = Vo[0];
}

// ---------------- plain scan (prologue only) ----------------
template<int NFULL, int TAIL, int PF>
__device__ __forceinline__ int row_scan(const float4* __restrict__ Sv, int npad,
                                        ushort* __restrict__ idxb,
                                        int lane, unsigned lt)
{
    constexpr int NT = NFULL + 1;
    const float4 z4 = make_float4(0.f, 0.f, 0.f, 0.f);
    float4 ring[PF];
#pragma unroll
    for (int p = 0; p < PF; ++p) {
        if (p < NT) ring[p] = (p < NFULL || lane < TAIL) ? __ldcs(Sv + p * 32 + lane) : z4;
        else        ring[p] = z4;
    }
    int cnt = 0;
#pragma unroll
    for (int it = 0; it < NT; ++it) {
        float4 v = ring[it % PF];
        if (it + PF < NT)
            ring[it % PF] = ((it + PF) < NFULL || lane < TAIL) ? __ldcs(Sv + (it + PF) * 32 + lane) : z4;
        unsigned m0 = __ballot_sync(0xffffffffu, v.x != 0.f);
        unsigned m1 = __ballot_sync(0xffffffffu, v.y != 0.f);
        unsigned m2 = __ballot_sync(0xffffffffu, v.z != 0.f);
        unsigned m3 = __ballot_sync(0xffffffffu, v.w != 0.f);
        int t0 = __popc(m0), t1 = __popc(m1), t2 = __popc(m2), t3 = __popc(m3);
        int p0 = cnt + __popc(m0 & lt);
        int p1 = cnt + t0 + __popc(m1 & lt);
        int p2 = cnt + t0 + t1 + __popc(m2 & lt);
        int p3 = cnt + t0 + t1 + t2 + __popc(m3 & lt);
        int base = (it * 32 + lane) * 4;
        if (v.x != 0.f) idxb[p0] = (ushort)(base);
        if (v.y != 0.f) idxb[p1] = (ushort)(base + 1);
        if (v.z != 0.f) idxb[p2] = (ushort)(base + 2);
        if (v.w != 0.f) idxb[p3] = (ushort)(base + 3);
        cnt += t0 + t1 + t2 + t3;
    }
    int cpad = (cnt + 7) & ~7;
    if (lane < cpad - cnt) idxb[cnt + lane] = (ushort)npad;  // dummy -> zero table row
    return cpad >> 3;
}

// one 8-index gather group from the smem table
__device__ __forceinline__ void g_group(uint4 w, const __half* __restrict__ tab, int jj,
                                        float& a0, float& a1)
{
    a0 += __half2float(tab[(w.x & 0xffffu) * SUB_NO + jj]);
    a1 += __half2float(tab[(w.x >> 16)     * SUB_NO + jj]);
    a0 += __half2float(tab[(w.y & 0xffffu) * SUB_NO + jj]);
    a1 += __half2float(tab[(w.y >> 16)     * SUB_NO + jj]);
    a0 += __half2float(tab[(w.z & 0xffffu) * SUB_NO + jj]);
    a1 += __half2float(tab[(w.z >> 16)     * SUB_NO + jj]);
    a0 += __half2float(tab[(w.w & 0xffffu) * SUB_NO + jj]);
    a1 += __half2float(tab[(w.w >> 16)     * SUB_NO + jj]);
}

// ---------------- fused: scan next row, gather current row ----------------
template<int NFULL, int TAIL, int PF>
__device__ __forceinline__ int scan_fused(const float4* __restrict__ Sv, int npad,
                                          ushort* __restrict__ idxN,
                                          const uint4* __restrict__ ibC, int nkC,
                                          const __half* __restrict__ tab, int jj,
                                          int lane, unsigned lt, float& res)
{
    constexpr int NT = NFULL + 1;
    const float4 z4 = make_float4(0.f, 0.f, 0.f, 0.f);
    float4 ring[PF];
#pragma unroll
    for (int p = 0; p < PF; ++p) {
        if (p < NT) ring[p] = (p < NFULL || lane < TAIL) ? __ldcs(Sv + p * 32 + lane) : z4;
        else        ring[p] = z4;
    }
    int cnt = 0, k = 0;
    float a0 = 0.f, a1 = 0.f;
#pragma unroll
    for (int it = 0; it < NT; ++it) {
        float4 v = ring[it % PF];
        if (it + PF < NT)
            ring[it % PF] = ((it + PF) < NFULL || lane < TAIL) ? __ldcs(Sv + (it + PF) * 32 + lane) : z4;
        unsigned m0 = __ballot_sync(0xffffffffu, v.x != 0.f);
        unsigned m1 = __ballot_sync(0xffffffffu, v.y != 0.f);
        unsigned m2 = __ballot_sync(0xffffffffu, v.z != 0.f);
        unsigned m3 = __ballot_sync(0xffffffffu, v.w != 0.f);
        int t0 = __popc(m0), t1 = __popc(m1), t2 = __popc(m2), t3 = __popc(m3);
        int p0 = cnt + __popc(m0 & lt);
        int p1 = cnt + t0 + __popc(m1 & lt);
        int p2 = cnt + t0 + t1 + __popc(m2 & lt);
        int p3 = cnt + t0 + t1 + t2 + __popc(m3 & lt);
        int base = (it * 32 + lane) * 4;
        if (v.x != 0.f) idxN[p0] = (ushort)(base);
        if (v.y != 0.f) idxN[p1] = (ushort)(base + 1);
        if (v.z != 0.f) idxN[p2] = (ushort)(base + 2);
        if (v.w != 0.f) idxN[p3] = (ushort)(base + 3);
        cnt += t0 + t1 + t2 + t3;
        // interleaved gather group of the CURRENT row (overlaps the ring LDGs)
        if (k < nkC) { g_group(ibC[k], tab, jj, a0, a1); ++k; }
    }
    // drain leftover gather groups
    for (; k < nkC; ++k) g_group(ibC[k], tab, jj, a0, a1);
    res = a0 + a1;
    int cpad = (cnt + 7) & ~7;
    if (lane < cpad - cnt) idxN[cnt + lane] = (ushort)npad;
    return cpad >> 3;
}

__device__ __forceinline__ float gather_s(const uint4* __restrict__ ib, int nk,
                                          const __half* __restrict__ tab, int jj)
{
    float a0 = 0.f, a1 = 0.f;
#pragma unroll 2
    for (int k = 0; k < nk; ++k) g_group(ib[k], tab, jj, a0, a1);
    return a0 + a1;
}

// ---------------- IIR+tree constants ----------------
#define CHU  32
#define NCH  (T_DATA / CHU)    // 625
#define NIT  (PAD + CHU)       // 80, compile-time
#define RD   16
#define PPB  8

__device__ __forceinline__ float fast_tanh(float x)
{
    x = fminf(fmaxf(x, -15.f), 15.f);
    float e = __expf(2.f * x);
    return __fdividef(e - 1.f, e + 1.f);
}

// ---------------- smem layout (dynamic, bytes) ----------------
#define SM_TABE 0                  // 80064
#define SM_TABI 80064              // 20064
#define SM_IDX  100128             // 16 warps x 1472 B (E:2x544, I:2x192)
#define WARP_IDX_BYTES 1472
#define SMEM_TOTAL (100128 + 16 * WARP_IDX_BYTES)   // 123680

// ---------------- THE mega-kernel ----------------
#define K2_THREADS 512
#define K2_WARPS   16
#define K2_BLOCKS  148         // one CTA per SM: co-resident, spin-safe
#define TOTW (K2_BLOCKS * K2_WARPS)   // 2368

__global__ void __launch_bounds__(K2_THREADS, 1)
mega_kernel(const float* __restrict__ Se, const float* __restrict__ Si,
            const float* __restrict__ Craw_e, const float* __restrict__ Craw_i,
            const float* __restrict__ Wsyn, const float* __restrict__ Tausyn,
            const float* __restrict__ Dsyn, const float* __restrict__ Wsub,
            const float* __restrict__ Vo, const float* __restrict__ Theta,
            float* __restrict__ out)
{
    extern __shared__ __align__(16) char smem[];
    const __half* tabE = (const __half*)(smem + SM_TABE);
    const __half* tabI = (const __half*)(smem + SM_TABI);

    // ---------- phase 0: prep slice ----------
    int gtid = blockIdx.x * K2_THREADS + threadIdx.x;
    if (gtid < N_PREP)
        do_prep(gtid, Craw_e, Craw_i, Wsyn, Tausyn, Dsyn, Wsub, Vo, Theta, out);
    __threadfence();
    __syncthreads();
    if (threadIdx.x == 0) atomicAdd(&g_A, 1);

    // ---------- phase 1: pipelined scan+gather ----------
    int warp = threadIdx.x >> 5;
    int lane = threadIdx.x & 31;
    unsigned lt = (1u << lane) - 1u;
    int jj = (lane < SUB_NO) ? lane : 0;
    char* wbase = smem + SM_IDX + warp * WARP_IDX_BYTES;
    ushort* idxE[2] = { (ushort*)wbase, (ushort*)(wbase + 544) };
    ushort* idxI[2] = { (ushort*)(wbase + 1088), (ushort*)(wbase + 1280) };

    int gwarp = blockIdx.x * K2_WARPS + warp;   // < 2368 < T_DATA: all warps active

    // prologue: scan first row (tables not needed yet)
    int row = gwarp, p = 0;
    int enk = row_scan<15, 20, 5>((const float4*)(Se + (size_t)row * E_NO), E_NO,
                                  idxE[0], lane, lt);
    int ink = row_scan<3, 29, 3>((const float4*)(Si + (size_t)row * I_NO), I_NO,
                                 idxI[0], lane, lt);
    __syncwarp();

    // wait for prep everywhere, then load tables into smem
    __syncthreads();
    if (threadIdx.x == 0)
        while (*(volatile int*)&g_A < K2_BLOCKS) __nanosleep(100);
    __syncthreads();
    __threadfence();
    {
        const uint4* ge = (const uint4*)g_THe;
        uint4* se = (uint4*)(smem + SM_TABE);
        for (int i = threadIdx.x; i < THE_N / 8; i += K2_THREADS) se[i] = ge[i];
        const uint4* gi = (const uint4*)g_THi;
        uint4* si = (uint4*)(smem + SM_TABI);
        for (int i = threadIdx.x; i < THI_N / 8; i += K2_THREADS) si[i] = gi[i];
    }
    __syncthreads();

    while (true) {
        int nrow = row + TOTW;
        float ae, ai;
        if (nrow < T_DATA) {
            int enkN = scan_fused<15, 20, 5>((const float4*)(Se + (size_t)nrow * E_NO), E_NO,
                                             idxE[1 - p], (const uint4*)idxE[p], enk,
                                             tabE, jj, lane, lt, ae);
            int inkN = scan_fused<3, 29, 3>((const float4*)(Si + (size_t)nrow * I_NO), I_NO,
                                            idxI[1 - p], (const uint4*)idxI[p], ink,
                                            tabI, jj, lane, lt, ai);
            __syncwarp();
            if (lane < SUB_NO) {
                g_synZe[(PAD + row) * SUB_NO + lane] = ae;
                g_synZi[(PAD + row) * SUB_NO + lane] = ai;
            }
            row = nrow; enk = enkN; ink = inkN; p ^= 1;
        } else {
            ae = gather_s((const uint4*)idxE[p], enk, tabE, jj);
            ai = gather_s((const uint4*)idxI[p], ink, tabI, jj);
            __syncwarp();
            if (lane < SUB_NO) {
                g_synZe[(PAD + row) * SUB_NO + lane] = ae;
                g_synZi[(PAD + row) * SUB_NO + lane] = ai;
            }
            break;
        }
    }

    // ---------- phase 2: grid-wide completion barrier ----------
    __threadfence();
    __syncthreads();
    if (threadIdx.x == 0) {
        atomicAdd(&g_S, 1);
        while (*(volatile int*)&g_S < K2_BLOCKS) __nanosleep(200);
    }
    __syncthreads();
    __threadfence();

    // ---------- phase 3: IIR + tree (tables dead; alias syn2 over them) ----------
    {
        float (*syn2)[2][CHU][21] = (float (*)[2][CHU][21])(smem);
        int w     = threadIdx.x >> 6;          // 0..7
        int type  = (threadIdx.x >> 5) & 1;
        int tlane = threadIdx.x & 31;
        int chunk = blockIdx.x * PPB + w;      // 148*8 = 1184 >= 625

        if (chunk < NCH && tlane < SUB_NO) {
            int s = tlane;
            const float* __restrict__ x = (type ? g_synZi : g_synZe) + chunk * CHU * SUB_NO + s;
            float r  = g_par[(type ? P_RI  : P_RE ) + s];
            float B  = g_par[(type ? P_BI  : P_BE ) + s];
            float BD = g_par[(type ? P_BDI : P_BDE) + s];
            float C1 = g_par[(type ? P_C1I : P_C1E) + s];

            float ring[RD];
#pragma unroll
            for (int q = 0; q < RD; ++q) ring[q] = x[q * SUB_NO];

            float s1 = 0.f, s2 = 0.f, xp = 0.f;
#pragma unroll
            for (int k = 0; k < NIT; ++k) {
                float xv = ring[k % RD];
                if (k + RD < NIT) ring[k % RD] = x[(k + RD) * SUB_NO];
                float ns2 = r * (s1 + s2);
                s1 = fmaf(r, s1, xv);
                s2 = ns2;
                if (k >= PAD)
                    syn2[w][type][k - PAD][s] = B * s2 - BD * s1 + BD * xv + C1 * xp;
                xp = xv;
            }
        }
        __syncthreads();

        if (chunk < NCH && type == 0) {
            int t = chunk * CHU + tlane;
            float syn[SUB_NO];
#pragma unroll
            for (int s = 0; s < SUB_NO; ++s)
                syn[s] = syn2[w][0][tlane][s] + syn2[w][1][tlane][s];

            float gain[SUB_NO], th[SUB_NO];
#pragma unroll
            for (int j = 0; j < SUB_NO; ++j) { gain[j] = g_par[P_GAIN + j]; th[j] = g_par[P_THETA + j]; }

            float sub[SUB_NO];
#pragma unroll
            for (int i = SUB_NO - 1; i >= 0; --i) {
                float vv = syn[i] + th[i];
                if (2 * i + 1 < SUB_NO) vv = fmaf(gain[2 * i + 1], sub[2 * i + 1], vv);
                if (2 * i + 2 < SUB_NO) vv = fmaf(gain[2 * i + 2], sub[2 * i + 2], vv);
                sub[i] = fast_tanh(vv);
            }
            out[t] = fmaf(sub[0], gain[0], g_par[P_VO]);
        }
    }

    // ---------- phase 4: last block out resets the barriers (replay-safe) ----------
    __syncthreads();
    if (threadIdx.x == 0) {
        int old = atomicAdd(&g_C, 1);
        if (old == K2_BLOCKS - 1) {   // all blocks passed g_S: nobody still spinning
            g_A = 0;
            g_S = 0;
            g_C = 0;
            __threadfence();
        }
    }
}

// ---------------- launch ----------------
extern "C" void kernel_launch(void* const* d_in, const int* in_sizes, int n_in,
                              void* d_out, int out_size)
{
    const float* Se     = (const float*)d_in[0];
    const float* Si     = (const float*)d_in[1];
    const float* Wsyn   = (const float*)d_in[3];
    const float* Tausyn = (const float*)d_in[4];
    const float* Dsyn   = (const float*)d_in[5];
    const float* Wsub   = (const float*)d_in[6];
    const float* Vo     = (const float*)d_in[7];
    const float* Theta  = (const float*)d_in[8];
    const float* Ce     = (const float*)d_in[9];
    const float* Ci     = (const float*)d_in[10];
    float* out = (float*)d_out;

    cudaFuncSetAttribute(mega_kernel, cudaFuncAttributeMaxDynamicSharedMemorySize, SMEM_TOTAL);
    mega_kernel<<<K2_BLOCKS, K2_THREADS, SMEM_TOTAL>>>(Se, Si, Ce, Ci, Wsyn, Tausyn, Dsyn,
                                                       Wsub, Vo, Theta, out);
}